// round 6
// baseline (speedup 1.0000x reference)
#include <cuda_runtime.h>
#include <cstdint>

// OneHotEncoder: per-row token histogram (skip pad_idx=0) -> float counts.
// tokens: [B, T] int32, out: [B, 32000] float32.
//
// R6 = R4 (f32 smem hist + TMA bulk store, 4-way vocab split) + two fixes:
//  (1) PreferredSharedMemoryCarveout = max  -> 7 CTAs/SM (224KB) instead of
//      the default-carveout limit of ~3 (R4 measured occ 42%). More resident
//      CTAs = zero/scan/atomics/TMA phases overlap across CTAs on each SM.
//  (2)

//      Prefetch the row's tokens into registers (2 x int4 per thread) BEFORE
//      the smem-zero loop, hiding the ~380cyc L2 token-load latency.
// fp32 smem atomicAdd is exact for integer counts; TMA writes each 32000B
// slice once, coalesced, offloaded from the LSU. Column 0 stays zero.

constexpr int VOCAB    = 32000;
constexpr int SPLIT    = 4;
constexpr int BINS     = VOCAB / SPLIT;   // 8000 floats = 32000 B per slice
constexpr int NTHREADS = 256;
constexpr int VPT      = 2;               // int4 vectors per thread (T=2048)

__global__ __launch_bounds__(NTHREADS, 7)
void onehot_hist_tma_kernel(const int4* __restrict__ tokens4,
                            float* __restrict__ out,
                            int vecs_per_row)   // T/4 = 512
{
    extern __shared__ float hist[];   // BINS floats = 32000 B

    const int cta = blockIdx.x;
    const int s   = cta & (SPLIT - 1);       // vocab slice index
    const int b   = cta >> 2;                // row index
    const int lo  = s * BINS;
    const int tid = threadIdx.x;

    // Prefetch this thread's share of the row (front-batched LDGs).
    const int4* __restrict__ trow = tokens4 + (size_t)b * vecs_per_row;
    int4 tv[VPT];
    #pragma unroll
    for (int v = 0; v < VPT; v++) {
        int i = tid + v * NTHREADS;
        tv[v] = (i < vecs_per_row) ? trow[i]
                                   : make_int4(0, 0, 0, 0);
    }

    // Zero the slice histogram while the loads are in flight.
    float4 z = make_float4(0.f, 0.f, 0.f, 0.f);
    #pragma unroll
    for (int i = tid; i < BINS / 4; i += NTHREADS) {
        reinterpret_cast<float4*>(hist)[i] = z;
    }
    __syncthreads();

    // Count tokens belonging to this slice (pad t==0 excluded; out-of-slice
    // excluded by the unsigned range check).
    #pragma unroll
    for (int v = 0; v < VPT; v++) {
        int4 t = tv[v];
        unsigned x;
        x = (unsigned)(t.x - lo); if (x < (unsigned)BINS && t.x != 0) atomicAdd(&hist[x], 1.0f);
        x = (unsigned)(t.y - lo); if (x < (unsigned)BINS && t.y != 0) atomicAdd(&hist[x], 1.0f);
        x = (unsigned)(t.z - lo); if (x < (unsigned)BINS && t.z != 0) atomicAdd(&hist[x], 1.0f);
        x = (unsigned)(t.w - lo); if (x < (unsigned)BINS && t.w != 0) atomicAdd(&hist[x], 1.0f);
    }
    __syncthreads();

    // One TMA 1-D bulk store writes the whole 32000B slice to global.
    if (tid == 0) {
        asm volatile("fence.proxy.async.shared::cta;" ::: "memory");
        uint32_t saddr = (uint32_t)__cvta_generic_to_shared(hist);
        float* gdst = out + (size_t)b * VOCAB + lo;   // 16B-aligned slices
        asm volatile(
            "cp.async.bulk.global.shared::cta.bulk_group [%0], [%1], %2;"
            :: "l"(gdst), "r"(saddr), "r"((unsigned)(BINS * sizeof(float)))
            : "memory");
        asm volatile("cp.async.bulk.commit_group;" ::: "memory");
        asm volatile("cp.async.bulk.wait_group 0;" ::: "memory");
    }
}

extern "C" void kernel_launch(void* const* d_in, const int* in_sizes, int n_in,
                              void* d_out, int out_size)
{
    const int* tokens = (const int*)d_in[0];   // [B, T] int32
    // d_in[1] = lengths [B] int32 — unused by the reference computation.

    const int B = in_sizes[1];                 // 256
    const int T = in_sizes[0] / B;             // 2048

    float* out = (float*)d_out;                // [B, VOCAB] float32

    const int smem_bytes = BINS * (int)sizeof(float);  // 32000
    cudaFuncSetAttribute(onehot_hist_tma_kernel,
                         cudaFuncAttributeMaxDynamicSharedMemorySize,
                         smem_bytes);
    // Max-shared carveout so 7 CTAs x 32KB fit per SM (default carveout
    // capped R4 at ~3 CTAs/SM -> occ 42%).
    cudaFuncSetAttribute(onehot_hist_tma_kernel,
                         cudaFuncAttributePreferredSharedMemoryCarveout,
                         cudaSharedmemCarveoutMaxShared);

    onehot_hist_tma_kernel<<<B * SPLIT, NTHREADS, smem_bytes>>>(
        (const int4*)tokens, out, T / 4);
}

// round 7
// speedup vs baseline: 1.2113x; 1.2113x over previous
#include <cuda_runtime.h>
#include <cstdint>

// OneHotEncoder: per-row token histogram (skip pad_idx=0) -> float counts.
// tokens: [B, T] int32, out: [B, 32000] float32.
//
// R7: f32 smem hist + TMA bulk store, but 8-way vocab split (4000 bins =
// 16KB/CTA). R4/R6 showed a hard residency cap of ~3.4 CTAs/SM at 32KB/CTA
// (occ stuck at 43% even with the carveout attribute) -> halving smem/CTA
// is the lever that actually raises resident CTAs (~6/SM expected).
// Chip-wide ATOMS / zero / TMA byte totals are unchanged by the split;
// only the token re-read grows (x8 = 16MB L2 reads, ~2.6K cyc, cheap).
// fp32 smem atomicAdd is exact for integer counts. Column 0 stays zero.

constexpr int VOCAB    = 32000;
constexpr int SPLIT    = 8;
constexpr int BINS     = VOCAB / SPLIT;   // 4000 floats = 16000 B per slice
constexpr int NTHREADS = 256;
constexpr int VPT      = 2;               // int4 vectors per thread (T=2048)

__global__ __launch_bounds__(NTHREADS, 6)
void onehot_hist_tma_kernel(const int4* __restrict__ tokens4,
                            float* __restrict__ out,
                            int vecs_per_row)   // T/4 = 512
{
    extern __shared__ float hist[];   // BINS floats = 16000 B

    const int cta = blockIdx.x;
    const int s   = cta & (SPLIT - 1);       // vocab slice index
    const int b   = cta >> 3;                // row index
    const int lo  = s * BINS;
    const int tid = threadIdx.x;

    // Prefetch this thread's share of the row (front-batched LDGs) so the
    // L2 load latency hides behind the smem-zero loop.
    const int4* __restrict__ trow = tokens4 + (size_t)b * vecs_per_row;
    int4 tv[VPT];
    #pragma unroll
    for (int v = 0; v < VPT; v++) {
        int i = tid + v * NTHREADS;
        tv[v] = (i < vecs_per_row) ? trow[i] : make_int4(0, 0, 0, 0);
    }

    // Zero the slice histogram (1000 float4 over 256 threads).
    float4 z = make_float4(0.f, 0.f, 0.f, 0.f);
    #pragma unroll
    for (int i = tid; i < BINS / 4; i += NTHREADS) {
        reinterpret_cast<float4*>(hist)[i] = z;
    }
    __syncthreads();

    // Count tokens in this slice (pad t==0 excluded; out-of-slice excluded
    // by the unsigned range check).
    #pragma unroll
    for (int v = 0; v < VPT; v++) {
        int4 t = tv[v];
        unsigned x;
        x = (unsigned)(t.x - lo); if (x < (unsigned)BINS && t.x != 0) atomicAdd(&hist[x], 1.0f);
        x = (unsigned)(t.y - lo); if (x < (unsigned)BINS && t.y != 0) atomicAdd(&hist[x], 1.0f);
        x = (unsigned)(t.z - lo); if (x < (unsigned)BINS && t.z != 0) atomicAdd(&hist[x], 1.0f);
        x = (unsigned)(t.w - lo); if (x < (unsigned)BINS && t.w != 0) atomicAdd(&hist[x], 1.0f);
    }
    __syncthreads();

    // One TMA 1-D bulk store writes the whole 16000B slice to global.
    if (tid == 0) {
        asm volatile("fence.proxy.async.shared::cta;" ::: "memory");
        uint32_t saddr = (uint32_t)__cvta_generic_to_shared(hist);
        float* gdst = out + (size_t)b * VOCAB + lo;   // 16B-aligned slices
        asm volatile(
            "cp.async.bulk.global.shared::cta.bulk_group [%0], [%1], %2;"
            :: "l"(gdst), "r"(saddr), "r"((unsigned)(BINS * sizeof(float)))
            : "memory");
        asm volatile("cp.async.bulk.commit_group;" ::: "memory");
        asm volatile("cp.async.bulk.wait_group 0;" ::: "memory");
    }
}

extern "C" void kernel_launch(void* const* d_in, const int* in_sizes, int n_in,
                              void* d_out, int out_size)
{
    const int* tokens = (const int*)d_in[0];   // [B, T] int32
    // d_in[1] = lengths [B] int32 — unused by the reference computation.

    const int B = in_sizes[1];                 // 256
    const int T = in_sizes[0] / B;             // 2048

    float* out = (float*)d_out;                // [B, VOCAB] float32

    const int smem_bytes = BINS * (int)sizeof(float);  // 16000
    cudaFuncSetAttribute(onehot_hist_tma_kernel,
                         cudaFuncAttributeMaxDynamicSharedMemorySize,
                         smem_bytes);
    cudaFuncSetAttribute(onehot_hist_tma_kernel,
                         cudaFuncAttributePreferredSharedMemoryCarveout,
                         cudaSharedmemCarveoutMaxShared);

    onehot_hist_tma_kernel<<<B * SPLIT, NTHREADS, smem_bytes>>>(
        (const int4*)tokens, out, T / 4);
}